// round 4
// baseline (speedup 1.0000x reference)
#include <cuda_runtime.h>
#include <math.h>

#define BS   16
#define NQ   128
#define T    480
#define P    72
#define TC   149               // 1 + 4 + 2*72 columns per target row
#define BN   (BS * NQ)         // 2048
#define TPAD 512
#define QT   4                 // queries per block in main phase
#define GRID 2048              // total blocks (power of two: ticket>>11)
#define NTB  120               // prep blocks for targets (4 warps each: 120*4=480)
#define NPREP 136              // 120 target blocks + 16 query blocks

// ---------------- device scratch (static init; monotonic counters are replay-safe) ----
__device__ int                g_mincnt = 0x7FFFFFFF;  // min valid-count (idempotent)
__device__ unsigned long long g_ticket = 0;           // monotonic block tickets
__device__ unsigned long long g_done   = 0;           // monotonic prep-done count
__device__ float4 g_tgt[TPAD * 6];                    // zero-init padding rows stay zero
__device__ float4 g_qry[BN * 5];

__device__ __forceinline__ float wred(float v) {
#pragma unroll
    for (int o = 16; o; o >>= 1) v += __shfl_xor_sync(0xffffffffu, v, o);
    return v;
}

__global__ void __launch_bounds__(128) fused(const float* __restrict__ logits,
                                             const float* __restrict__ curves,
                                             const float* __restrict__ tgt,
                                             float* __restrict__ out) {
    const int b   = blockIdx.x;
    const int tid = threadIdx.x;

    // ================= Phase A: prep (blocks 0..NPREP-1) =================
    if (b < NTB) {
        // warp-per-target moments, coalesced point loads; 4 warps -> 4 targets/block
        int warp = tid >> 5, lane = tid & 31;
        int t = b * 4 + warp;                      // 120*4 = 480
        const float* row = tgt + t * TC;

        float idf = row[0];
        float ly = row[1], uy = row[2], lx = row[3], ux = row[4];
        float dx = ux - lx, dy = uy - ly;
        float inv = 1.0f / (dx * dx + dy * dy);

        float S0=0.f,S1=0.f,S2=0.f,S3=0.f,S4=0.f,S5=0.f,S6=0.f,Kt=0.f;
        float Tx0=0.f,Tx1=0.f,Tx2=0.f,Tx3=0.f,Ty0=0.f,Ty1=0.f,Ty2=0.f,Ty3=0.f;
#pragma unroll
        for (int p = lane; p < P; p += 32) {
            float tx = row[5 + p];
            float ty = row[5 + P + p];
            if (tx >= 0.0f) {
                float lam = (dx * (tx - lx) + dy * (ty - ly)) * inv;
                float l2 = lam * lam, l3 = l2 * lam;
                S0 += 1.0f; S1 += lam; S2 += l2; S3 += l3;
                S4 += l2 * l2; S5 += l2 * l3; S6 += l3 * l3;
                Tx0 += tx; Tx1 += tx * lam; Tx2 += tx * l2; Tx3 += tx * l3;
                Ty0 += ty; Ty1 += ty * lam; Ty2 += ty * l2; Ty3 += ty * l3;
                Kt  += tx * tx + ty * ty;
            }
        }
        S0=wred(S0); S1=wred(S1); S2=wred(S2); S3=wred(S3);
        S4=wred(S4); S5=wred(S5); S6=wred(S6); Kt=wred(Kt);
        Tx0=wred(Tx0); Tx1=wred(Tx1); Tx2=wred(Tx2); Tx3=wred(Tx3);
        Ty0=wred(Ty0); Ty1=wred(Ty1); Ty2=wred(Ty2); Ty3=wred(Ty3);

        if (lane == 0) {
            float s  = 0.1f * rsqrtf(S0);          // sqrt(min_per) applied in main phase
            float m2 = -2.0f * s;
            g_tgt[t * 6 + 0] = make_float4(s * S0, s * S1, s * S2, s * S3);
            g_tgt[t * 6 + 1] = make_float4(s * S4, s * S5, s * S6, s * Kt);
            g_tgt[t * 6 + 2] = make_float4(m2 * Tx0, m2 * Tx1, m2 * Tx2, m2 * Tx3);
            g_tgt[t * 6 + 3] = make_float4(m2 * Ty0, m2 * Ty1, m2 * Ty2, m2 * Ty3);
            g_tgt[t * 6 + 4] = make_float4(ly, uy, lx, ux);
            g_tgt[t * 6 + 5] = make_float4(idf, 0.f, 0.f, 0.f);
            atomicMin(&g_mincnt, (int)S0);
        }
        __syncthreads();
        if (tid == 0) { __threadfence(); atomicAdd(&g_done, 1ULL); }
    } else if (b < NPREP) {
        // per-query softmax + polynomial self-product coeffs
        int q = (b - NTB) * 128 + tid;             // 16*128 = 2048
        float l0 = logits[q * 3 + 0], l1 = logits[q * 3 + 1], l2 = logits[q * 3 + 2];
        float m  = fmaxf(l0, fmaxf(l1, l2));
        float e0 = expf(l0 - m), e1 = expf(l1 - m), e2 = expf(l2 - m);
        float ninv = -1.0f / (e0 + e1 + e2);
        float np0 = e0 * ninv, np1 = e1 * ninv, np2 = e2 * ninv;   // = -softmax

        const float* ob = curves + q * 8;
        float ob0 = ob[0], ob1 = ob[1], ob2 = ob[2], ob3 = ob[3];
        float ob4 = ob[4], ob5 = ob[5], ob6 = ob[6], ob7 = ob[7];
        float a0 = ob2, a2 = ob5, a3 = ob4, a1 = ob3 - a3 - a2 - ob2;
        float b0 = ob0, b2 = ob7, b3 = ob6, b1 = ob1 - b3 - b2 - ob0;

        float C0 = a0 * a0 + b0 * b0;
        float C1 = 2.f * (a0 * a1 + b0 * b1);
        float C2 = a1 * a1 + b1 * b1 + 2.f * (a0 * a2 + b0 * b2);
        float C3 = 2.f * (a0 * a3 + a1 * a2 + b0 * b3 + b1 * b2);
        float C4 = a2 * a2 + b2 * b2 + 2.f * (a1 * a3 + b1 * b3);
        float C5 = 2.f * (a2 * a3 + b2 * b3);
        float C6 = a3 * a3 + b3 * b3;

        g_qry[q * 5 + 0] = make_float4(C0, C1, C2, C3);
        g_qry[q * 5 + 1] = make_float4(C4, C5, C6, a0);
        g_qry[q * 5 + 2] = make_float4(a1, a2, a3, b0);
        g_qry[q * 5 + 3] = make_float4(b1, b2, b3, ob1);
        g_qry[q * 5 + 4] = make_float4(ob3, np0, np1, np2);
        __syncthreads();
        if (tid == 0) { __threadfence(); atomicAdd(&g_done, 1ULL); }
    }

    // ================= Barrier: wait for this launch's NPREP increments ==========
    // Launches are stream-serialized, so each launch's GRID tickets are contiguous.
    if (tid == 0) {
        unsigned long long ticket = atomicAdd(&g_ticket, 1ULL);
        unsigned long long target = ((ticket >> 11) + 1ULL) * (unsigned long long)NPREP;
        while (*(volatile unsigned long long*)&g_done < target) __nanosleep(64);
    }
    __syncthreads();
    __threadfence();   // acquire prep writes

    // ================= Phase B: main 2048x480 pair computation ====================
    __shared__ float4 sq[QT * 5];
    int xb = b & 3;                 // t-tile (4 x 128 = 512)
    int qb = (b >> 2) * QT;         // 512 query groups * 4

    if (tid < QT * 5) sq[tid] = g_qry[qb * 5 + tid];

    int t = xb * 128 + tid;
    float4 A = g_tgt[t * 6 + 0];
    float4 B = g_tgt[t * 6 + 1];
    float4 X = g_tgt[t * 6 + 2];
    float4 Y = g_tgt[t * 6 + 3];
    float4 E = g_tgt[t * 6 + 4];
    int   id = (int)g_tgt[t * 6 + 5].x;
    float sm = sqrtf((float)g_mincnt);
    __syncthreads();

    bool ok = (t < T);

#pragma unroll
    for (int qi = 0; qi < QT; qi++) {
        float4 qv0 = sq[qi * 5 + 0];
        float4 qv1 = sq[qi * 5 + 1];
        float4 qv2 = sq[qi * 5 + 2];
        float4 qv3 = sq[qi * 5 + 3];
        float4 qv4 = sq[qi * 5 + 4];

        float v0 = B.w, v1 = 0.f, v2 = 0.f, v3 = 0.f;
        v0 = fmaf(qv0.x, A.x, v0);
        v1 = fmaf(qv0.y, A.y, v1);
        v2 = fmaf(qv0.z, A.z, v2);
        v3 = fmaf(qv0.w, A.w, v3);
        v0 = fmaf(qv1.x, B.x, v0);
        v1 = fmaf(qv1.y, B.y, v1);
        v2 = fmaf(qv1.z, B.z, v2);
        v3 = fmaf(qv1.w, X.x, v3);
        v0 = fmaf(qv2.x, X.y, v0);
        v1 = fmaf(qv2.y, X.z, v1);
        v2 = fmaf(qv2.z, X.w, v2);
        v3 = fmaf(qv2.w, Y.x, v3);
        v0 = fmaf(qv3.x, Y.y, v0);
        v1 = fmaf(qv3.y, Y.z, v1);
        v2 = fmaf(qv3.z, Y.w, v2);

        float cls = (id == 0) ? qv4.y : ((id == 1) ? qv4.z : qv4.w);
        float low = 0.5f * (fabsf(qv2.w - E.x) + fabsf(qv1.w - E.z));
        float up  = 0.5f * (fabsf(qv3.w - E.y) + fabsf(qv4.x - E.w));

        float r = fmaf(sm, (v0 + v1) + (v2 + v3), cls + low + up);
        if (ok) out[(qb + qi) * T + t] = r;
    }
}

// ---------------- launcher ----------------
extern "C" void kernel_launch(void* const* d_in, const int* in_sizes, int n_in,
                              void* d_out, int out_size) {
    const float* logits = (const float*)d_in[0];
    const float* curves = (const float*)d_in[1];
    const float* tgt    = (const float*)d_in[2];
    float* out          = (float*)d_out;

    fused<<<GRID, 128>>>(logits, curves, tgt, out);
}

// round 5
// speedup vs baseline: 1.2832x; 1.2832x over previous
#include <cuda_runtime.h>
#include <math.h>

#define BS   16
#define NQ   128
#define T    480
#define P    72
#define TC   149               // 1 + 4 + 2*72 columns per target row
#define BN   (BS * NQ)         // 2048
#define TPAD 512
#define QT   4                 // queries per block in main kernel
#define NTB  120               // target-prep blocks (4 warps each: 120*4=480)

// ---------------- device scratch ----------------
__device__ int    g_mincnt = 0x7FFFFFFF;   // min valid-count (idempotent across replays)
__device__ float4 g_tgt[TPAD * 6];         // zero-init padding rows stay zero

__device__ __forceinline__ float wred(float v) {
#pragma unroll
    for (int o = 16; o; o >>= 1) v += __shfl_xor_sync(0xffffffffu, v, o);
    return v;
}

// ---------------- k_prep: per-target moments (warp per target) ----------------
__global__ void __launch_bounds__(128) k_prep(const float* __restrict__ tgt) {
    int warp = threadIdx.x >> 5, lane = threadIdx.x & 31;
    int t = blockIdx.x * 4 + warp;                 // 120*4 = 480
    const float* row = tgt + t * TC;

    float idf = row[0];
    float ly = row[1], uy = row[2], lx = row[3], ux = row[4];
    float dx = ux - lx, dy = uy - ly;
    float inv = 1.0f / (dx * dx + dy * dy);

    float S0=0.f,S1=0.f,S2=0.f,S3=0.f,S4=0.f,S5=0.f,S6=0.f,Kt=0.f;
    float Tx0=0.f,Tx1=0.f,Tx2=0.f,Tx3=0.f,Ty0=0.f,Ty1=0.f,Ty2=0.f,Ty3=0.f;
#pragma unroll
    for (int p = lane; p < P; p += 32) {           // coalesced across lanes
        float tx = row[5 + p];
        float ty = row[5 + P + p];
        if (tx >= 0.0f) {
            float lam = (dx * (tx - lx) + dy * (ty - ly)) * inv;
            float l2 = lam * lam, l3 = l2 * lam;
            S0 += 1.0f; S1 += lam; S2 += l2; S3 += l3;
            S4 += l2 * l2; S5 += l2 * l3; S6 += l3 * l3;
            Tx0 += tx; Tx1 += tx * lam; Tx2 += tx * l2; Tx3 += tx * l3;
            Ty0 += ty; Ty1 += ty * lam; Ty2 += ty * l2; Ty3 += ty * l3;
            Kt  += tx * tx + ty * ty;
        }
    }
    S0=wred(S0); S1=wred(S1); S2=wred(S2); S3=wred(S3);
    S4=wred(S4); S5=wred(S5); S6=wred(S6); Kt=wred(Kt);
    Tx0=wred(Tx0); Tx1=wred(Tx1); Tx2=wred(Tx2); Tx3=wred(Tx3);
    Ty0=wred(Ty0); Ty1=wred(Ty1); Ty2=wred(Ty2); Ty3=wred(Ty3);

    if (lane == 0) {
        float s  = 0.1f * rsqrtf(S0);              // sqrt(min_per) applied in k_main
        float m2 = -2.0f * s;
        g_tgt[t * 6 + 0] = make_float4(s * S0, s * S1, s * S2, s * S3);
        g_tgt[t * 6 + 1] = make_float4(s * S4, s * S5, s * S6, s * Kt);
        g_tgt[t * 6 + 2] = make_float4(m2 * Tx0, m2 * Tx1, m2 * Tx2, m2 * Tx3);
        g_tgt[t * 6 + 3] = make_float4(m2 * Ty0, m2 * Ty1, m2 * Ty2, m2 * Ty3);
        g_tgt[t * 6 + 4] = make_float4(ly, uy, lx, ux);
        g_tgt[t * 6 + 5] = make_float4(idf, 0.f, 0.f, 0.f);
        atomicMin(&g_mincnt, (int)S0);
    }
}

// ---------------- k_main: query prep inline + 2048x480 pair computation --------
// Launched with PDL: starts while k_prep runs; query prep overlaps; gridsync
// before consuming g_tgt.
__global__ void __launch_bounds__(128) k_main(const float* __restrict__ logits,
                                              const float* __restrict__ curves,
                                              float* __restrict__ out) {
    __shared__ float4 sq[QT * 5];
    const int tid = threadIdx.x;
    const int xb  = blockIdx.x & 3;                // t-tile (4 x 128 = 512)
    const int qb  = (blockIdx.x >> 2) * QT;        // 512 query groups

    // ---- inline query prep (redundant per block; 4 threads, broadcast loads) ----
    if (tid < QT) {
        int q = qb + tid;
        float l0 = logits[q * 3 + 0], l1 = logits[q * 3 + 1], l2 = logits[q * 3 + 2];
        float m  = fmaxf(l0, fmaxf(l1, l2));
        float e0 = expf(l0 - m), e1 = expf(l1 - m), e2 = expf(l2 - m);
        float ninv = -1.0f / (e0 + e1 + e2);
        float np0 = e0 * ninv, np1 = e1 * ninv, np2 = e2 * ninv;   // = -softmax

        const float* obp = curves + q * 8;
        float ob0 = obp[0], ob1 = obp[1], ob2 = obp[2], ob3 = obp[3];
        float ob4 = obp[4], ob5 = obp[5], ob6 = obp[6], ob7 = obp[7];
        float a0 = ob2, a2 = ob5, a3 = ob4, a1 = ob3 - a3 - a2 - ob2;
        float b0 = ob0, b2 = ob7, b3 = ob6, b1 = ob1 - b3 - b2 - ob0;

        float C0 = a0 * a0 + b0 * b0;
        float C1 = 2.f * (a0 * a1 + b0 * b1);
        float C2 = a1 * a1 + b1 * b1 + 2.f * (a0 * a2 + b0 * b2);
        float C3 = 2.f * (a0 * a3 + a1 * a2 + b0 * b3 + b1 * b2);
        float C4 = a2 * a2 + b2 * b2 + 2.f * (a1 * a3 + b1 * b3);
        float C5 = 2.f * (a2 * a3 + b2 * b3);
        float C6 = a3 * a3 + b3 * b3;

        sq[tid * 5 + 0] = make_float4(C0, C1, C2, C3);
        sq[tid * 5 + 1] = make_float4(C4, C5, C6, a0);
        sq[tid * 5 + 2] = make_float4(a1, a2, a3, b0);
        sq[tid * 5 + 3] = make_float4(b1, b2, b3, ob1);
        sq[tid * 5 + 4] = make_float4(ob3, np0, np1, np2);
    }

    // ---- wait for k_prep's writes to be visible ----
    cudaGridDependencySynchronize();
    __syncthreads();

    int t = xb * 128 + tid;
    float4 A = g_tgt[t * 6 + 0];
    float4 B = g_tgt[t * 6 + 1];
    float4 X = g_tgt[t * 6 + 2];
    float4 Y = g_tgt[t * 6 + 3];
    float4 E = g_tgt[t * 6 + 4];
    int   id = (int)g_tgt[t * 6 + 5].x;
    float sm = sqrtf((float)g_mincnt);
    bool  ok = (t < T);

#pragma unroll
    for (int qi = 0; qi < QT; qi++) {
        float4 qv0 = sq[qi * 5 + 0];
        float4 qv1 = sq[qi * 5 + 1];
        float4 qv2 = sq[qi * 5 + 2];
        float4 qv3 = sq[qi * 5 + 3];
        float4 qv4 = sq[qi * 5 + 4];

        float v0 = B.w, v1 = 0.f, v2 = 0.f, v3 = 0.f;
        v0 = fmaf(qv0.x, A.x, v0);
        v1 = fmaf(qv0.y, A.y, v1);
        v2 = fmaf(qv0.z, A.z, v2);
        v3 = fmaf(qv0.w, A.w, v3);
        v0 = fmaf(qv1.x, B.x, v0);
        v1 = fmaf(qv1.y, B.y, v1);
        v2 = fmaf(qv1.z, B.z, v2);
        v3 = fmaf(qv1.w, X.x, v3);
        v0 = fmaf(qv2.x, X.y, v0);
        v1 = fmaf(qv2.y, X.z, v1);
        v2 = fmaf(qv2.z, X.w, v2);
        v3 = fmaf(qv2.w, Y.x, v3);
        v0 = fmaf(qv3.x, Y.y, v0);
        v1 = fmaf(qv3.y, Y.z, v1);
        v2 = fmaf(qv3.z, Y.w, v2);

        float cls = (id == 0) ? qv4.y : ((id == 1) ? qv4.z : qv4.w);
        float low = 0.5f * (fabsf(qv2.w - E.x) + fabsf(qv1.w - E.z));
        float up  = 0.5f * (fabsf(qv3.w - E.y) + fabsf(qv4.x - E.w));

        float r = fmaf(sm, (v0 + v1) + (v2 + v3), cls + low + up);
        if (ok) out[(qb + qi) * T + t] = r;
    }
}

// ---------------- launcher ----------------
extern "C" void kernel_launch(void* const* d_in, const int* in_sizes, int n_in,
                              void* d_out, int out_size) {
    const float* logits = (const float*)d_in[0];
    const float* curves = (const float*)d_in[1];
    const float* tgt    = (const float*)d_in[2];
    float* out          = (float*)d_out;

    k_prep<<<NTB, 128>>>(tgt);

    cudaLaunchConfig_t cfg = {};
    cfg.gridDim  = dim3(BN / QT * 4);   // 2048 blocks
    cfg.blockDim = dim3(128);
    cudaLaunchAttribute attr[1];
    attr[0].id = cudaLaunchAttributeProgrammaticStreamSerialization;
    attr[0].val.programmaticStreamSerializationAllowed = 1;
    cfg.attrs    = attr;
    cfg.numAttrs = 1;
    cudaLaunchKernelEx(&cfg, k_main, logits, curves, out);
}

// round 6
// speedup vs baseline: 1.4927x; 1.1633x over previous
#include <cuda_runtime.h>
#include <math.h>

#define BS   16
#define NQ   128
#define T    480
#define P    72
#define TC   149               // 1 + 4 + 2*72 columns per target row
#define BN   (BS * NQ)         // 2048
#define TPAD 512
#define QT   8                 // queries per block
#define NTB  120               // target-prep blocks (4 warps each: 120*4=480)

// ---------------- device scratch ----------------
__device__ int    g_mincnt = 0x7FFFFFFF;   // min valid-count (idempotent across replays)
__device__ float4 g_tgt[TPAD * 6];         // zero-init padding rows stay zero

__device__ __forceinline__ float wred(float v) {
#pragma unroll
    for (int o = 16; o; o >>= 1) v += __shfl_xor_sync(0xffffffffu, v, o);
    return v;
}

// ---------------- k_prep: per-target moments (warp per target) ----------------
__global__ void __launch_bounds__(128) k_prep(const float* __restrict__ tgt) {
    int warp = threadIdx.x >> 5, lane = threadIdx.x & 31;
    int t = blockIdx.x * 4 + warp;                 // 120*4 = 480
    const float* row = tgt + t * TC;

    float idf = row[0];
    float ly = row[1], uy = row[2], lx = row[3], ux = row[4];
    float dx = ux - lx, dy = uy - ly;
    float inv = 1.0f / (dx * dx + dy * dy);

    float S0=0.f,S1=0.f,S2=0.f,S3=0.f,S4=0.f,S5=0.f,S6=0.f,Kt=0.f;
    float Tx0=0.f,Tx1=0.f,Tx2=0.f,Tx3=0.f,Ty0=0.f,Ty1=0.f,Ty2=0.f,Ty3=0.f;
#pragma unroll
    for (int p = lane; p < P; p += 32) {           // coalesced across lanes
        float tx = row[5 + p];
        float ty = row[5 + P + p];
        if (tx >= 0.0f) {
            float lam = (dx * (tx - lx) + dy * (ty - ly)) * inv;
            float l2 = lam * lam, l3 = l2 * lam;
            S0 += 1.0f; S1 += lam; S2 += l2; S3 += l3;
            S4 += l2 * l2; S5 += l2 * l3; S6 += l3 * l3;
            Tx0 += tx; Tx1 += tx * lam; Tx2 += tx * l2; Tx3 += tx * l3;
            Ty0 += ty; Ty1 += ty * lam; Ty2 += ty * l2; Ty3 += ty * l3;
            Kt  += tx * tx + ty * ty;
        }
    }
    S0=wred(S0); S1=wred(S1); S2=wred(S2); S3=wred(S3);
    S4=wred(S4); S5=wred(S5); S6=wred(S6); Kt=wred(Kt);
    Tx0=wred(Tx0); Tx1=wred(Tx1); Tx2=wred(Tx2); Tx3=wred(Tx3);
    Ty0=wred(Ty0); Ty1=wred(Ty1); Ty2=wred(Ty2); Ty3=wred(Ty3);

    if (lane == 0) {
        float s  = 0.1f * rsqrtf(S0);              // sqrt(min_per) applied in k_main
        float m2 = -2.0f * s;
        g_tgt[t * 6 + 0] = make_float4(s * S0, s * S1, s * S2, s * S3);
        g_tgt[t * 6 + 1] = make_float4(s * S4, s * S5, s * S6, s * Kt);
        g_tgt[t * 6 + 2] = make_float4(m2 * Tx0, m2 * Tx1, m2 * Tx2, m2 * Tx3);
        g_tgt[t * 6 + 3] = make_float4(m2 * Ty0, m2 * Ty1, m2 * Ty2, m2 * Ty3);
        g_tgt[t * 6 + 4] = make_float4(ly, uy, lx, ux);
        g_tgt[t * 6 + 5] = make_float4(idf, 0.f, 0.f, 0.f);
        atomicMin(&g_mincnt, (int)S0);
    }
}

// ---------------- k_main: 2 targets/thread, QT queries/block -------------------
// grid = 2 t-tiles(256) x 256 q-groups = 512 blocks x 128 threads.
// PDL: inline query prep runs before gridsync (overlaps k_prep).
__global__ void __launch_bounds__(128) k_main(const float* __restrict__ logits,
                                              const float* __restrict__ curves,
                                              float* __restrict__ out) {
    __shared__ float4 sq[QT * 5];
    const int tid  = threadIdx.x;
    const int tile = blockIdx.x & 1;               // t-tile of 256
    const int qb   = (blockIdx.x >> 1) * QT;       // 256 query groups

    // ---- inline query prep (QT threads; before gridsync, overlaps k_prep) ----
    if (tid < QT) {
        int q = qb + tid;
        float l0 = logits[q * 3 + 0], l1 = logits[q * 3 + 1], l2 = logits[q * 3 + 2];
        float m  = fmaxf(l0, fmaxf(l1, l2));
        float e0 = expf(l0 - m), e1 = expf(l1 - m), e2 = expf(l2 - m);
        float ninv = -1.0f / (e0 + e1 + e2);
        float np0 = e0 * ninv, np1 = e1 * ninv, np2 = e2 * ninv;   // = -softmax

        const float* obp = curves + q * 8;
        float ob0 = obp[0], ob1 = obp[1], ob2 = obp[2], ob3 = obp[3];
        float ob4 = obp[4], ob5 = obp[5], ob6 = obp[6], ob7 = obp[7];
        float a0 = ob2, a2 = ob5, a3 = ob4, a1 = ob3 - a3 - a2 - ob2;
        float b0 = ob0, b2 = ob7, b3 = ob6, b1 = ob1 - b3 - b2 - ob0;

        float C0 = a0 * a0 + b0 * b0;
        float C1 = 2.f * (a0 * a1 + b0 * b1);
        float C2 = a1 * a1 + b1 * b1 + 2.f * (a0 * a2 + b0 * b2);
        float C3 = 2.f * (a0 * a3 + a1 * a2 + b0 * b3 + b1 * b2);
        float C4 = a2 * a2 + b2 * b2 + 2.f * (a1 * a3 + b1 * b3);
        float C5 = 2.f * (a2 * a3 + b2 * b3);
        float C6 = a3 * a3 + b3 * b3;

        sq[tid * 5 + 0] = make_float4(C0, C1, C2, C3);
        sq[tid * 5 + 1] = make_float4(C4, C5, C6, a0);
        sq[tid * 5 + 2] = make_float4(a1, a2, a3, b0);
        sq[tid * 5 + 3] = make_float4(b1, b2, b3, ob1);
        sq[tid * 5 + 4] = make_float4(ob3, np0, np1, np2);
    }

    // ---- wait for k_prep's writes ----
    cudaGridDependencySynchronize();
    __syncthreads();

    const int t0 = tile * 256 + tid;        // [0,128) or [256,384) -> always < T
    const int t1 = t0 + 128;                // [128,256) or [384,512)
    const bool ok1 = (t1 < T);

    float4 A0 = g_tgt[t0 * 6 + 0], A1 = g_tgt[t1 * 6 + 0];
    float4 B0 = g_tgt[t0 * 6 + 1], B1 = g_tgt[t1 * 6 + 1];
    float4 X0 = g_tgt[t0 * 6 + 2], X1 = g_tgt[t1 * 6 + 2];
    float4 Y0 = g_tgt[t0 * 6 + 3], Y1 = g_tgt[t1 * 6 + 3];
    float4 E0 = g_tgt[t0 * 6 + 4], E1 = g_tgt[t1 * 6 + 4];
    int   id0 = (int)g_tgt[t0 * 6 + 5].x;
    int   id1 = (int)g_tgt[t1 * 6 + 5].x;
    float sm  = sqrtf((float)g_mincnt);

#pragma unroll
    for (int qi = 0; qi < QT; qi++) {
        float4 qv0 = sq[qi * 5 + 0];
        float4 qv1 = sq[qi * 5 + 1];
        float4 qv2 = sq[qi * 5 + 2];
        float4 qv3 = sq[qi * 5 + 3];
        float4 qv4 = sq[qi * 5 + 4];

        // target 0 chains
        float u0 = B0.w, u1 = 0.f, u2 = 0.f, u3 = 0.f;
        // target 1 chains
        float w0 = B1.w, w1 = 0.f, w2 = 0.f, w3 = 0.f;

        u0 = fmaf(qv0.x, A0.x, u0);  w0 = fmaf(qv0.x, A1.x, w0);
        u1 = fmaf(qv0.y, A0.y, u1);  w1 = fmaf(qv0.y, A1.y, w1);
        u2 = fmaf(qv0.z, A0.z, u2);  w2 = fmaf(qv0.z, A1.z, w2);
        u3 = fmaf(qv0.w, A0.w, u3);  w3 = fmaf(qv0.w, A1.w, w3);
        u0 = fmaf(qv1.x, B0.x, u0);  w0 = fmaf(qv1.x, B1.x, w0);
        u1 = fmaf(qv1.y, B0.y, u1);  w1 = fmaf(qv1.y, B1.y, w1);
        u2 = fmaf(qv1.z, B0.z, u2);  w2 = fmaf(qv1.z, B1.z, w2);
        u3 = fmaf(qv1.w, X0.x, u3);  w3 = fmaf(qv1.w, X1.x, w3);
        u0 = fmaf(qv2.x, X0.y, u0);  w0 = fmaf(qv2.x, X1.y, w0);
        u1 = fmaf(qv2.y, X0.z, u1);  w1 = fmaf(qv2.y, X1.z, w1);
        u2 = fmaf(qv2.z, X0.w, u2);  w2 = fmaf(qv2.z, X1.w, w2);
        u3 = fmaf(qv2.w, Y0.x, u3);  w3 = fmaf(qv2.w, Y1.x, w3);
        u0 = fmaf(qv3.x, Y0.y, u0);  w0 = fmaf(qv3.x, Y1.y, w0);
        u1 = fmaf(qv3.y, Y0.z, u1);  w1 = fmaf(qv3.y, Y1.z, w1);
        u2 = fmaf(qv3.z, Y0.w, u2);  w2 = fmaf(qv3.z, Y1.w, w2);

        float cls0 = (id0 == 0) ? qv4.y : ((id0 == 1) ? qv4.z : qv4.w);
        float cls1 = (id1 == 0) ? qv4.y : ((id1 == 1) ? qv4.z : qv4.w);
        float low0 = 0.5f * (fabsf(qv2.w - E0.x) + fabsf(qv1.w - E0.z));
        float low1 = 0.5f * (fabsf(qv2.w - E1.x) + fabsf(qv1.w - E1.z));
        float up0  = 0.5f * (fabsf(qv3.w - E0.y) + fabsf(qv4.x - E0.w));
        float up1  = 0.5f * (fabsf(qv3.w - E1.y) + fabsf(qv4.x - E1.w));

        float r0 = fmaf(sm, (u0 + u1) + (u2 + u3), cls0 + low0 + up0);
        float r1 = fmaf(sm, (w0 + w1) + (w2 + w3), cls1 + low1 + up1);

        float* orow = out + (qb + qi) * T;
        orow[t0] = r0;
        if (ok1) orow[t1] = r1;
    }
}

// ---------------- launcher ----------------
extern "C" void kernel_launch(void* const* d_in, const int* in_sizes, int n_in,
                              void* d_out, int out_size) {
    const float* logits = (const float*)d_in[0];
    const float* curves = (const float*)d_in[1];
    const float* tgt    = (const float*)d_in[2];
    float* out          = (float*)d_out;

    k_prep<<<NTB, 128>>>(tgt);

    cudaLaunchConfig_t cfg = {};
    cfg.gridDim  = dim3(2 * (BN / QT));   // 512 blocks
    cfg.blockDim = dim3(128);
    cudaLaunchAttribute attr[1];
    attr[0].id = cudaLaunchAttributeProgrammaticStreamSerialization;
    attr[0].val.programmaticStreamSerializationAllowed = 1;
    cfg.attrs    = attr;
    cfg.numAttrs = 1;
    cudaLaunchKernelEx(&cfg, k_main, logits, curves, out);
}